// round 12
// baseline (speedup 1.0000x reference)
#include <cuda_runtime.h>
#include <cstdint>

// MaskLayer: per-(batch,channel) spatial argmax -> L1-distance mask -> scale.
// x, out: [B, 14, 14, 512] float32, channel-innermost.
//
// R10 = R5 (best measured: one-shot CTAs, DTILE=64, 50KB smem, 4 CTAs/SM,
// plain 16B stores) + ONE lever: cp.async.cg with .L2::256B prefetch hint.
// Every spatial position is a 256B-aligned, 256B-contiguous gmem segment at
// DTILE=64, so the hint requests full 256B DRAM granules with zero overfetch.
//
// Session evidence: occupancy (24/47/96%), issue diet, phase decorrelation,
// and explicit pipelining all leave DRAM% at 83-85% and dur at ~121.5us ->
// mixed R/W HBM turnaround ceiling (~6.7 TB/s) is the binding roofline.

static constexpr int IMGS     = 14;
static constexpr int SPATIAL  = IMGS * IMGS;              // 196
static constexpr int DEPTH    = 512;
static constexpr int DTILE    = 64;                       // channels per CTA
static constexpr int BLOCK    = 128;
static constexpr int TILE_FLOATS = SPATIAL * DTILE;       // 12544
static constexpr int TILE_VEC4   = TILE_FLOATS / 4;       // 3136
static constexpr int ITERS    = (TILE_VEC4 + BLOCK - 1) / BLOCK;  // 25 (last: warps 0-1)
static constexpr int SMEM_BYTES = TILE_FLOATS * (int)sizeof(float);  // 50176

static constexpr float NEG_BIG = -3.402823466e38f;

__device__ __forceinline__ uint32_t smem_u32(const void* p) {
    return (uint32_t)__cvta_generic_to_shared(p);
}

__global__ void __launch_bounds__(BLOCK, 4)
mask_layer_kernel(const float* __restrict__ x, float* __restrict__ out) {
    extern __shared__ float tile[];        // [SPATIAL][DTILE]
    __shared__ int sidx[DTILE];            // packed (row | col<<16) per channel

    const int tid = threadIdx.x;
    const int dt  = blockIdx.x & 7;        // DEPTH / DTILE = 8 tiles per batch
    const int b   = blockIdx.x >> 3;
    const size_t base = (size_t)b * (SPATIAL * DEPTH) + (size_t)dt * DTILE;
    const float* __restrict__ src = x + base;

    // ---- Phase A: stage tile via cp.async.cg + L2::256B (16B, L1-bypass) ----
    // idx -> (s = idx>>4, c4 = (idx&15)*4). Each spatial position is 256B
    // contiguous AND 256B-aligned in gmem; warp covers 2 positions (512B).
#pragma unroll
    for (int k = 0; k < ITERS; k++) {
        int idx = tid + k * BLOCK;
        if (idx < TILE_VEC4) {             // warp-uniform (k=24: warps 0-1 only)
            int s  = idx >> 4;
            int c4 = (idx & 15) << 2;
            uint32_t d = smem_u32(tile + s * DTILE + c4);
            const float* g = src + (size_t)s * DEPTH + c4;
            asm volatile("cp.async.cg.shared.global.L2::256B [%0], [%1], 16;\n"
                         :: "r"(d), "l"(g));
        }
    }
    asm volatile("cp.async.commit_group;\ncp.async.wait_group 0;\n" ::: "memory");
    __syncthreads();

    // ---- Phase B: per-channel argmax(rowmax) / argmax(colmax) ----
    // 128 threads / 64 channels: both halves redundantly compute channel
    // c = tid & 63 (conflict-free LDS, no combine needed).
    // Strict '>' with ascending index == jnp.argmax first-occurrence.
    {
        const int c = tid & (DTILE - 1);
        float colmax[IMGS];
#pragma unroll
        for (int j = 0; j < IMGS; j++) colmax[j] = NEG_BIG;

        float bestRow = NEG_BIG;
        int rowIdx = 0;
#pragma unroll 2
        for (int i = 0; i < IMGS; i++) {
            float rmax = NEG_BIG;
#pragma unroll
            for (int j = 0; j < IMGS; j++) {
                float v = tile[(i * IMGS + j) * DTILE + c];
                rmax = fmaxf(rmax, v);
                colmax[j] = fmaxf(colmax[j], v);
            }
            if (rmax > bestRow) { bestRow = rmax; rowIdx = i; }
        }
        int colIdx = 0;
        float bestCol = colmax[0];
#pragma unroll
        for (int j = 1; j < IMGS; j++)
            if (colmax[j] > bestCol) { bestCol = colmax[j]; colIdx = j; }

        if (tid < DTILE) sidx[c] = rowIdx | (colIdx << 16);
    }
    __syncthreads();

    // ---- Phase C: apply mask, vectorized 16B stores ----
    const float TAUF = 0.5f / 196.0f;               // TAU
    const float TC   = TAUF * (4.0f / 14.0f);       // TAU * BETA / IMG_SIZE
    float* __restrict__ dstg = out + base;

#pragma unroll 5
    for (int k = 0; k < ITERS; k++) {
        int idx = tid + k * BLOCK;
        if (idx < TILE_VEC4) {
            int s  = idx >> 4;
            int c4 = (idx & 15) << 2;
            int i  = s / IMGS;
            int j  = s - i * IMGS;

            float4 v = *(const float4*)(tile + s * DTILE + c4);
            int4   p = *(const int4*)(sidx + c4);

            // mask = TAU*max(1 - COEF*l1, -1) = max(TAU - (TAU*COEF)*l1, -TAU)
            auto msk = [&](int pk) -> float {
                int r  = pk & 0xFFFF;
                int cc = pk >> 16;
                int l1 = abs(i - r) + abs(j - cc);
                return fmaxf(fmaf((float)l1, -TC, TAUF), -TAUF);
            };

            float4 o;
            o.x = msk(p.x) * v.x;
            o.y = msk(p.y) * v.y;
            o.z = msk(p.z) * v.z;
            o.w = msk(p.w) * v.w;
            *(float4*)(dstg + (size_t)s * DEPTH + c4) = o;
        }
    }
}

extern "C" void kernel_launch(void* const* d_in, const int* in_sizes, int n_in,
                              void* d_out, int out_size) {
    (void)n_in; (void)out_size;
    const float* x = (const float*)d_in[0];
    float* out = (float*)d_out;

    int n = in_sizes[0];                                  // B * 196 * 512
    int batches = n / (SPATIAL * DEPTH);                  // 1024
    int grid = batches * (DEPTH / DTILE);                 // 8192

    // Host-side attribute call: immediate, deterministic, capture-safe.
    cudaFuncSetAttribute(mask_layer_kernel,
                         cudaFuncAttributeMaxDynamicSharedMemorySize, SMEM_BYTES);

    mask_layer_kernel<<<grid, BLOCK, SMEM_BYTES>>>(x, out);
}

// round 13
// speedup vs baseline: 1.0024x; 1.0024x over previous
#include <cuda_runtime.h>
#include <cstdint>

// MaskLayer: per-(batch,channel) spatial argmax -> L1-distance mask -> scale.
// x, out: [B, 14, 14, 512] float32, channel-innermost.
//
// FINAL (= R5, best measured 121.3us): one-shot CTAs, DTILE=64 -> 50KB smem
// -> 4 CTAs/SM (launch_bounds(128,4)). cp.async.cg staging (single DRAM
// read), smem-resident argmax reduction, plain STG.128 stores.
//
// Session evidence for convergence: occupancy 24/47/96%, issue-diet, phase
// decorrelation, explicit double-buffering, L2::256B hints, and __stcs were
// all tested; every variant lands at 83-85% DRAM / ~121.5us except __stcs
// and 1-CTA/SM pipelining, which regressed. 822MB compulsory traffic at the
// measured ~7.1TB/s effective mixed-R/W throughput == the HBM turnaround
// roofline for this part. This kernel is at it.

static constexpr int IMGS     = 14;
static constexpr int SPATIAL  = IMGS * IMGS;              // 196
static constexpr int DEPTH    = 512;
static constexpr int DTILE    = 64;                       // channels per CTA
static constexpr int BLOCK    = 128;
static constexpr int TILE_FLOATS = SPATIAL * DTILE;       // 12544
static constexpr int TILE_VEC4   = TILE_FLOATS / 4;       // 3136
static constexpr int ITERS    = (TILE_VEC4 + BLOCK - 1) / BLOCK;  // 25 (last: warps 0-1)
static constexpr int SMEM_BYTES = TILE_FLOATS * (int)sizeof(float);  // 50176

static constexpr float NEG_BIG = -3.402823466e38f;

__device__ __forceinline__ uint32_t smem_u32(const void* p) {
    return (uint32_t)__cvta_generic_to_shared(p);
}

__global__ void __launch_bounds__(BLOCK, 4)
mask_layer_kernel(const float* __restrict__ x, float* __restrict__ out) {
    extern __shared__ float tile[];        // [SPATIAL][DTILE]
    __shared__ int sidx[DTILE];            // packed (row | col<<16) per channel

    const int tid = threadIdx.x;
    const int dt  = blockIdx.x & 7;        // DEPTH / DTILE = 8 tiles per batch
    const int b   = blockIdx.x >> 3;
    const size_t base = (size_t)b * (SPATIAL * DEPTH) + (size_t)dt * DTILE;
    const float* __restrict__ src = x + base;

    // ---- Phase A: stage tile via cp.async.cg (16B, L1-bypass) ----
    // idx -> (s = idx>>4, c4 = (idx&15)*4). Each spatial position is 256B
    // contiguous in gmem; a warp covers 2 positions (512B). Smem conflict-free.
#pragma unroll
    for (int k = 0; k < ITERS; k++) {
        int idx = tid + k * BLOCK;
        if (idx < TILE_VEC4) {             // warp-uniform (k=24: warps 0-1 only)
            int s  = idx >> 4;
            int c4 = (idx & 15) << 2;
            uint32_t d = smem_u32(tile + s * DTILE + c4);
            const float* g = src + (size_t)s * DEPTH + c4;
            asm volatile("cp.async.cg.shared.global [%0], [%1], 16;\n"
                         :: "r"(d), "l"(g));
        }
    }
    asm volatile("cp.async.commit_group;\ncp.async.wait_group 0;\n" ::: "memory");
    __syncthreads();

    // ---- Phase B: per-channel argmax(rowmax) / argmax(colmax) ----
    // 128 threads / 64 channels: both halves redundantly compute channel
    // c = tid & 63 (conflict-free LDS, no combine needed).
    // Strict '>' with ascending index == jnp.argmax first-occurrence.
    {
        const int c = tid & (DTILE - 1);
        float colmax[IMGS];
#pragma unroll
        for (int j = 0; j < IMGS; j++) colmax[j] = NEG_BIG;

        float bestRow = NEG_BIG;
        int rowIdx = 0;
#pragma unroll 2
        for (int i = 0; i < IMGS; i++) {
            float rmax = NEG_BIG;
#pragma unroll
            for (int j = 0; j < IMGS; j++) {
                float v = tile[(i * IMGS + j) * DTILE + c];
                rmax = fmaxf(rmax, v);
                colmax[j] = fmaxf(colmax[j], v);
            }
            if (rmax > bestRow) { bestRow = rmax; rowIdx = i; }
        }
        int colIdx = 0;
        float bestCol = colmax[0];
#pragma unroll
        for (int j = 1; j < IMGS; j++)
            if (colmax[j] > bestCol) { bestCol = colmax[j]; colIdx = j; }

        if (tid < DTILE) sidx[c] = rowIdx | (colIdx << 16);
    }
    __syncthreads();

    // ---- Phase C: apply mask, vectorized 16B stores ----
    const float TAUF = 0.5f / 196.0f;               // TAU
    const float TC   = TAUF * (4.0f / 14.0f);       // TAU * BETA / IMG_SIZE
    float* __restrict__ dstg = out + base;

#pragma unroll 5
    for (int k = 0; k < ITERS; k++) {
        int idx = tid + k * BLOCK;
        if (idx < TILE_VEC4) {
            int s  = idx >> 4;
            int c4 = (idx & 15) << 2;
            int i  = s / IMGS;
            int j  = s - i * IMGS;

            float4 v = *(const float4*)(tile + s * DTILE + c4);
            int4   p = *(const int4*)(sidx + c4);

            // mask = TAU*max(1 - COEF*l1, -1) = max(TAU - (TAU*COEF)*l1, -TAU)
            auto msk = [&](int pk) -> float {
                int r  = pk & 0xFFFF;
                int cc = pk >> 16;
                int l1 = abs(i - r) + abs(j - cc);
                return fmaxf(fmaf((float)l1, -TC, TAUF), -TAUF);
            };

            float4 o;
            o.x = msk(p.x) * v.x;
            o.y = msk(p.y) * v.y;
            o.z = msk(p.z) * v.z;
            o.w = msk(p.w) * v.w;
            *(float4*)(dstg + (size_t)s * DEPTH + c4) = o;
        }
    }
}

extern "C" void kernel_launch(void* const* d_in, const int* in_sizes, int n_in,
                              void* d_out, int out_size) {
    (void)n_in; (void)out_size;
    const float* x = (const float*)d_in[0];
    float* out = (float*)d_out;

    int n = in_sizes[0];                                  // B * 196 * 512
    int batches = n / (SPATIAL * DEPTH);                  // 1024
    int grid = batches * (DEPTH / DTILE);                 // 8192

    // Host-side attribute call: immediate, deterministic, capture-safe.
    cudaFuncSetAttribute(mask_layer_kernel,
                         cudaFuncAttributeMaxDynamicSharedMemorySize, SMEM_BYTES);

    mask_layer_kernel<<<grid, BLOCK, SMEM_BYTES>>>(x, out);
}